// round 7
// baseline (speedup 1.0000x reference)
#include <cuda_runtime.h>

#define NTHR 128
#define HALO 2048
#define SMEM_BYTES ((2 * HALO + 8192) * 4)   // 49152 B

__device__ __forceinline__ float2 ffma2(float2 a, float2 b, float2 c) {
    float2 d;
    asm("fma.rn.f32x2 %0, %1, %2, %3;"
        : "=l"(reinterpret_cast<unsigned long long&>(d))
        : "l"(reinterpret_cast<unsigned long long&>(a)),
          "l"(reinterpret_cast<unsigned long long&>(b)),
          "l"(reinterpret_cast<unsigned long long&>(c)));
    return d;
}

// epilogue for ONE position; zp[i] = (z_{k=2i}, z_{k=2i+1})
__device__ __forceinline__ void epi_pos(const float2 zp[4], bool valid,
                                        float cmax[8], unsigned& clo, unsigned& chi)
{
    float v[8];
#pragma unroll
    for (int i = 0; i < 4; i++) { v[2 * i] = zp[i].x; v[2 * i + 1] = zp[i].y; }
    float m = fmaxf(fmaxf(fmaxf(v[0], v[1]), fmaxf(v[2], v[3])),
                    fmaxf(fmaxf(v[4], v[5]), fmaxf(v[6], v[7])));
    float n = fminf(fminf(fminf(v[0], v[1]), fminf(v[2], v[3])),
                    fminf(fminf(v[4], v[5]), fminf(v[6], v[7])));
#pragma unroll
    for (int k = 0; k < 8; k++)
        if (valid && v[k] == m) cmax[k] += m;
#pragma unroll
    for (int k = 0; k < 4; k++)
        if (valid && v[k] == n) clo += (1u << (8 * k));
#pragma unroll
    for (int k = 4; k < 8; k++)
        if (valid && v[k] == n) chi += (1u << (8 * (k - 4)));
}

__global__ __launch_bounds__(NTHR, 4)
void hydra_kernel(const float* __restrict__ X, const float* __restrict__ W,
                  const int* __restrict__ I, float* __restrict__ out)
{
    extern __shared__ float sm[];
    float*        A  = sm;
    float4*       A4 = (float4*)A;
    const float2* A2 = (const float2*)A;

    const int bid = blockIdx.x;
    const int g   = bid & 31;
    const int j   = (bid >> 5) & 1;
    const int di  = (bid >> 6) % 10;
    const int b   = bid / 640;
    const int d   = 1 << di;
    const int tid = threadIdx.x;

    // ---- zero halos only (interior overwritten by gather) ----
#pragma unroll
    for (int i = tid; i < 512; i += NTHR) {
        A4[i] = make_float4(0.f, 0.f, 0.f, 0.f);                 // left halo
        A4[(HALO + 8192) / 4 + i] = make_float4(0.f, 0.f, 0.f, 0.f); // right halo
    }

    // ---- weights -> registers, k-pair packed: wp2[r*4+i] = (w_{2i,r}, w_{2i+1,r}) ----
    const float* Wb = W + ((di * 2 + j) * 256 + g * 8) * 9;
    float2 wp2[36];
#pragma unroll
    for (int r = 0; r < 9; r++)
#pragma unroll
        for (int i = 0; i < 4; i++)
            wp2[r * 4 + i] = make_float2(__ldg(Wb + (2 * i) * 9 + r),
                                         __ldg(Wb + (2 * i + 1) * 9 + r));

    const int* Ib = I + ((di * 2 + j) * 32 + g) * 6;
    const int ic0 = Ib[0], ic1 = Ib[1], ic2 = Ib[2], ic3 = Ib[3], ic4 = Ib[4], ic5 = Ib[5];

    __syncthreads();

    // ---- channel-gather sum into interior [HALO, HALO+8192) ----
    const float4* X4 = (const float4*)X;
    const int rb = b * 12 * 2048;
#pragma unroll 2
    for (int t = tid; t < 2048; t += NTHR) {
        float4 s = X4[rb + ic0 * 2048 + t];
        float4 v;
        v = X4[rb + ic1 * 2048 + t]; s.x += v.x; s.y += v.y; s.z += v.z; s.w += v.w;
        v = X4[rb + ic2 * 2048 + t]; s.x += v.x; s.y += v.y; s.z += v.z; s.w += v.w;
        v = X4[rb + ic3 * 2048 + t]; s.x += v.x; s.y += v.y; s.z += v.z; s.w += v.w;
        v = X4[rb + ic4 * 2048 + t]; s.x += v.x; s.y += v.y; s.z += v.z; s.w += v.w;
        v = X4[rb + ic5 * 2048 + t]; s.x += v.x; s.y += v.y; s.z += v.z; s.w += v.w;
        A4[HALO / 4 + t] = s;
    }
    __syncthreads();

    // ---- j==1: in-place first difference, 2 barriers ----
    int nPos = 8192;
    if (j == 1) {
        nPos = 8191;
        const int cbase = HALO + tid * 64;
        const float bnd = A[cbase + 64];       // tid==127 reads right-halo zero
        __syncthreads();
        float4* C4 = (float4*)(A + cbase);
        float4 v = C4[0];
#pragma unroll
        for (int i4 = 0; i4 < 16; i4++) {
            float4 vn;
            if (i4 < 15) vn = C4[i4 + 1];
            else         vn = make_float4(bnd, 0.f, 0.f, 0.f);
            float4 o;
            o.x = v.y - v.x; o.y = v.z - v.y; o.z = v.w - v.z; o.w = vn.x - v.w;
            C4[i4] = o;
            v = vn;
        }
        if (tid == NTHR - 1) A[HALO + 8191] = 0.f;
        __syncthreads();
    }

    // ---- main loop: 32 iterations x 1 position-pair/thread ----
    float cmax[8];
    unsigned clo = 0u, chi = 0u;
#pragma unroll
    for (int k = 0; k < 8; k++) cmax[k] = 0.f;

    if (d == 1) {
#pragma unroll 1
        for (int t = 0; t < 32; t++) {
            const int p = t * 128 + tid;
            float2 v0 = A2[1022 + p], v1 = A2[1023 + p], v2 = A2[1024 + p],
                   v3 = A2[1025 + p], v4 = A2[1026 + p];
            float2 dup[10];
            dup[0] = make_float2(v0.x, v0.x); dup[1] = make_float2(v0.y, v0.y);
            dup[2] = make_float2(v1.x, v1.x); dup[3] = make_float2(v1.y, v1.y);
            dup[4] = make_float2(v2.x, v2.x); dup[5] = make_float2(v2.y, v2.y);
            dup[6] = make_float2(v3.x, v3.x); dup[7] = make_float2(v3.y, v3.y);
            dup[8] = make_float2(v4.x, v4.x); dup[9] = make_float2(v4.y, v4.y);
            float2 za[4], zb[4];
#pragma unroll
            for (int i = 0; i < 4; i++) { za[i] = make_float2(0.f, 0.f); zb[i] = make_float2(0.f, 0.f); }
#pragma unroll
            for (int r = 0; r < 9; r++)
#pragma unroll
                for (int i = 0; i < 4; i++) {
                    za[i] = ffma2(wp2[r * 4 + i], dup[r],     za[i]);
                    zb[i] = ffma2(wp2[r * 4 + i], dup[r + 1], zb[i]);
                }
            epi_pos(za, true,              cmax, clo, chi);
            epi_pos(zb, (2 * p + 1) < nPos, cmax, clo, chi);
        }
    } else {
        const int hd = d >> 1;
#pragma unroll 1
        for (int t = 0; t < 32; t++) {
            const int p = t * 128 + tid;
            float2 za[4], zb[4];
#pragma unroll
            for (int i = 0; i < 4; i++) { za[i] = make_float2(0.f, 0.f); zb[i] = make_float2(0.f, 0.f); }
#pragma unroll
            for (int r = 0; r < 9; r++) {
                const float2 v = A2[1024 + p + (r - 4) * hd];   // (x_p0, x_p1)
                const float2 d0 = make_float2(v.x, v.x);
                const float2 d1 = make_float2(v.y, v.y);
#pragma unroll
                for (int i = 0; i < 4; i++) {
                    za[i] = ffma2(wp2[r * 4 + i], d0, za[i]);
                    zb[i] = ffma2(wp2[r * 4 + i], d1, zb[i]);
                }
            }
            epi_pos(za, true,              cmax, clo, chi);
            epi_pos(zb, (2 * p + 1) < nPos, cmax, clo, chi);
        }
    }

    // ---- block reduction (A reused as scratch) ----
    __syncthreads();
    if (tid < 16) ((unsigned*)A)[tid] = 0u;
    __syncthreads();

    const int lane = tid & 31;
#pragma unroll
    for (int k = 0; k < 8; k++) {
        float v = cmax[k];
        int   c = (int)((k < 4 ? (clo >> (8 * k)) : (chi >> (8 * (k - 4)))) & 0xFFu);
#pragma unroll
        for (int off = 16; off; off >>= 1) {
            v += __shfl_down_sync(0xffffffffu, v, off);
            c += __shfl_down_sync(0xffffffffu, c, off);
        }
        if (lane == 0) {
            atomicAdd(&A[k], v);
            atomicAdd((int*)A + 8 + k, c);
        }
    }
    __syncthreads();

    // ---- outputs ----
    const int rowBase = ((di * 2 + j) * 2) * 32 + g;
    if (tid < 8) {
        float v = A[tid];
        out[(b * 1280 + rowBase) * 8 + tid] = v > 0.f ? v : 0.f;
    } else if (tid < 16) {
        const int k = tid - 8;
        const int c = ((const int*)A)[8 + k];
        out[(b * 1280 + rowBase + 32) * 8 + k] = (float)c;
    }
}

extern "C" void kernel_launch(void* const* d_in, const int* in_sizes, int n_in,
                              void* d_out, int out_size)
{
    const float* X = (const float*)d_in[0];
    const float* W = (const float*)d_in[1];
    const int*   I = (const int*)d_in[2];
    float*       O = (float*)d_out;

    cudaFuncSetAttribute(hydra_kernel, cudaFuncAttributeMaxDynamicSharedMemorySize, SMEM_BYTES);
    hydra_kernel<<<20480, NTHR, SMEM_BYTES>>>(X, W, I, O);
}

// round 9
// speedup vs baseline: 1.0573x; 1.0573x over previous
#include <cuda_runtime.h>

#define NTHR 128
#define HALO 2048
#define SMEM_BYTES ((2 * HALO + 8192) * 4)   // 49152 B

__device__ __forceinline__ float2 ffma2(float2 a, float2 b, float2 c) {
    float2 d;
    asm("fma.rn.f32x2 %0, %1, %2, %3;"
        : "=l"(reinterpret_cast<unsigned long long&>(d))
        : "l"(reinterpret_cast<unsigned long long&>(a)),
          "l"(reinterpret_cast<unsigned long long&>(b)),
          "l"(reinterpret_cast<unsigned long long&>(c)));
    return d;
}

// epilogue for one position-pair:
// LSB index embedding -> distinct values; FMNMX trees; bitwise-eq max
// histogram; shift-based packed min counter.
__device__ __forceinline__ void epi_pair(const float2 z[8], bool v1ok,
                                         float cmax[8], unsigned long long& cnt)
{
    float fx[8], fy[8];
#pragma unroll
    for (int k = 0; k < 8; k++) {
        fx[k] = __uint_as_float((__float_as_uint(z[k].x) & ~7u) | (unsigned)k);
        fy[k] = __uint_as_float((__float_as_uint(z[k].y) & ~7u) | (unsigned)k);
    }
    float mx = fmaxf(fmaxf(fmaxf(fx[0], fx[1]), fmaxf(fx[2], fx[3])),
                     fmaxf(fmaxf(fx[4], fx[5]), fmaxf(fx[6], fx[7])));
    float nx = fminf(fminf(fminf(fx[0], fx[1]), fminf(fx[2], fx[3])),
                     fminf(fminf(fx[4], fx[5]), fminf(fx[6], fx[7])));
    float my = fmaxf(fmaxf(fmaxf(fy[0], fy[1]), fmaxf(fy[2], fy[3])),
                     fmaxf(fmaxf(fy[4], fy[5]), fmaxf(fy[6], fy[7])));
    float ny = fminf(fminf(fminf(fy[0], fy[1]), fminf(fy[2], fy[3])),
                     fminf(fminf(fy[4], fy[5]), fminf(fy[6], fy[7])));

    const unsigned mux = __float_as_uint(mx);
    const unsigned muy = __float_as_uint(my);
#pragma unroll
    for (int k = 0; k < 8; k++) {
        if (__float_as_uint(fx[k]) == mux)          cmax[k] += mx;
        if (v1ok && __float_as_uint(fy[k]) == muy)  cmax[k] += my;
    }
    cnt += 1ull << (8u * (__float_as_uint(nx) & 7u));
    if (v1ok) cnt += 1ull << (8u * (__float_as_uint(ny) & 7u));
}

__global__ __launch_bounds__(NTHR, 2)
void hydra_kernel(const float* __restrict__ X, const float* __restrict__ W,
                  const int* __restrict__ I, float* __restrict__ out)
{
    extern __shared__ float sm[];
    float*        A  = sm;
    float4*       A4 = (float4*)A;
    const float2* A2 = (const float2*)A;

    const int bid = blockIdx.x;
    const int g   = bid & 31;
    const int j   = (bid >> 5) & 1;
    const int di  = (bid >> 6) % 10;
    const int b   = bid / 640;
    const int d   = 1 << di;
    const int tid = threadIdx.x;

    // ---- zero halos only (gather overwrites the interior) ----
#pragma unroll
    for (int i = tid; i < 512; i += NTHR) {
        A4[i] = make_float4(0.f, 0.f, 0.f, 0.f);
        A4[(HALO + 8192) / 4 + i] = make_float4(0.f, 0.f, 0.f, 0.f);
    }

    // ---- weights -> registers, duplicated for f32x2 ----
    const float* Wb = W + ((di * 2 + j) * 256 + g * 8) * 9;
    float2 wp[72];
#pragma unroll
    for (int i = 0; i < 72; i++) { float w = __ldg(Wb + i); wp[i] = make_float2(w, w); }

    const int* Ib = I + ((di * 2 + j) * 32 + g) * 6;
    const int ic0 = Ib[0], ic1 = Ib[1], ic2 = Ib[2], ic3 = Ib[3], ic4 = Ib[4], ic5 = Ib[5];

    __syncthreads();

    // ---- channel-gather sum into interior [HALO, HALO+8192) ----
    const float4* X4 = (const float4*)X;
    const int rb = b * 12 * 2048;
#pragma unroll 2
    for (int t = tid; t < 2048; t += NTHR) {
        float4 s = X4[rb + ic0 * 2048 + t];
        float4 v;
        v = X4[rb + ic1 * 2048 + t]; s.x += v.x; s.y += v.y; s.z += v.z; s.w += v.w;
        v = X4[rb + ic2 * 2048 + t]; s.x += v.x; s.y += v.y; s.z += v.z; s.w += v.w;
        v = X4[rb + ic3 * 2048 + t]; s.x += v.x; s.y += v.y; s.z += v.z; s.w += v.w;
        v = X4[rb + ic4 * 2048 + t]; s.x += v.x; s.y += v.y; s.z += v.z; s.w += v.w;
        v = X4[rb + ic5 * 2048 + t]; s.x += v.x; s.y += v.y; s.z += v.z; s.w += v.w;
        A4[HALO / 4 + t] = s;
    }
    __syncthreads();

    // ---- j==1: in-place first difference, 2 barriers ----
    int nPos = 8192;
    if (j == 1) {
        nPos = 8191;
        const int cbase = HALO + tid * 64;
        const float bnd = A[cbase + 64];       // tid==127 reads right-halo zero
        __syncthreads();
        float4* C4 = (float4*)(A + cbase);
        float4 v = C4[0];
#pragma unroll
        for (int i4 = 0; i4 < 16; i4++) {
            float4 vn;
            if (i4 < 15) vn = C4[i4 + 1];
            else         vn = make_float4(bnd, 0.f, 0.f, 0.f);
            float4 o;
            o.x = v.y - v.x; o.y = v.z - v.y; o.z = v.w - v.z; o.w = vn.x - v.w;
            C4[i4] = o;
            v = vn;
        }
        if (tid == NTHR - 1) A[HALO + 8191] = 0.f;
        __syncthreads();
    }

    // ---- main loop: 32 iterations x 1 position-pair/thread ----
    float cmax[8];
    unsigned long long cnt = 0ull;
#pragma unroll
    for (int k = 0; k < 8; k++) cmax[k] = 0.f;

    if (d == 1) {
#pragma unroll 1
        for (int t = 0; t < 32; t++) {
            const int p = t * 128 + tid;
            float2 v0 = A2[1022 + p], v1 = A2[1023 + p], v2 = A2[1024 + p],
                   v3 = A2[1025 + p], v4 = A2[1026 + p];
            float2 xv[9];
            xv[0] = v0; xv[2] = v1; xv[4] = v2; xv[6] = v3; xv[8] = v4;
            xv[1] = make_float2(v0.y, v1.x);
            xv[3] = make_float2(v1.y, v2.x);
            xv[5] = make_float2(v2.y, v3.x);
            xv[7] = make_float2(v3.y, v4.x);
            float2 z[8];
#pragma unroll
            for (int k = 0; k < 8; k++) z[k] = make_float2(0.f, 0.f);
#pragma unroll
            for (int r = 0; r < 9; r++) {
                const float2 x2 = xv[r];
#pragma unroll
                for (int k = 0; k < 8; k++) z[k] = ffma2(wp[k * 9 + r], x2, z[k]);
            }
            epi_pair(z, (2 * p + 1) < nPos, cmax, cnt);
        }
    } else {
        const int hd = d >> 1;
#pragma unroll 1
        for (int t = 0; t < 32; t++) {
            const int p = t * 128 + tid;
            float2 z[8];
#pragma unroll
            for (int k = 0; k < 8; k++) z[k] = make_float2(0.f, 0.f);
#pragma unroll
            for (int r = 0; r < 9; r++) {
                const float2 x2 = A2[1024 + p + (r - 4) * hd];
#pragma unroll
                for (int k = 0; k < 8; k++) z[k] = ffma2(wp[k * 9 + r], x2, z[k]);
            }
            epi_pair(z, (2 * p + 1) < nPos, cmax, cnt);
        }
    }

    // ---- block reduction (A reused as scratch) ----
    __syncthreads();
    if (tid < 16) ((unsigned*)A)[tid] = 0u;
    __syncthreads();

    const int lane = tid & 31;
#pragma unroll
    for (int k = 0; k < 8; k++) {
        float v = cmax[k];
        int   c = (int)((cnt >> (8 * k)) & 0xFFull);
#pragma unroll
        for (int off = 16; off; off >>= 1) {
            v += __shfl_down_sync(0xffffffffu, v, off);
            c += __shfl_down_sync(0xffffffffu, c, off);
        }
        if (lane == 0) {
            atomicAdd(&A[k], v);
            atomicAdd((int*)A + 8 + k, c);
        }
    }
    __syncthreads();

    // ---- outputs ----
    const int rowBase = ((di * 2 + j) * 2) * 32 + g;
    if (tid < 8) {
        float v = A[tid];
        out[(b * 1280 + rowBase) * 8 + tid] = v > 0.f ? v : 0.f;
    } else if (tid < 16) {
        const int k = tid - 8;
        const int c = ((const int*)A)[8 + k];
        out[(b * 1280 + rowBase + 32) * 8 + k] = (float)c;
    }
}

extern "C" void kernel_launch(void* const* d_in, const int* in_sizes, int n_in,
                              void* d_out, int out_size)
{
    const float* X = (const float*)d_in[0];
    const float* W = (const float*)d_in[1];
    const int*   I = (const int*)d_in[2];
    float*       O = (float*)d_out;

    cudaFuncSetAttribute(hydra_kernel, cudaFuncAttributeMaxDynamicSharedMemorySize, SMEM_BYTES);
    hydra_kernel<<<20480, NTHR, SMEM_BYTES>>>(X, W, I, O);
}